// round 16
// baseline (speedup 1.0000x reference)
#include <cuda_runtime.h>
#include <cuda_bf16.h>

typedef unsigned long long u64;
typedef unsigned int u32;
typedef unsigned short u16;

#define B_  128
#define T_  512
#define D_  300
#define H_  128
#define KP1 320   // layer0 K padded (300 -> 320, 10 chunks of 32)
#define KP2 256   // layer1 K (8 chunks of 32)

// ---------------- static device scratch ----------------
// bf16 hi/lo interleaved as one u32 word per element: word = hi_bits | (lo_bits << 16)
__device__ u32   g_ABw [(size_t)B_ * T_ * KP1];    // embeddings packed
__device__ float g_xg0 [(size_t)B_ * T_ * 1024];   // layer0 preacts (fwd 0:512, rev 512:1024)
__device__ float g_h0  [(size_t)B_ * T_ * 256];    // layer0 output fp32 (only t=T-1 written)
__device__ u32   g_h0w [(size_t)B_ * T_ * 256];    // layer0 output packed
__device__ float g_xg1 [(size_t)B_ * T_ * 512];    // layer1-fwd preacts
__device__ u32   g_B1w [1024 * KP1];               // W_ih layer0 (f||r), [n][k] packed
__device__ u32   g_B2w [512 * KP2];                // W_ih layer1-fwd, [n][k] packed
__device__ float g_bias0[1024];
__device__ float g_bias1[512];

// ---------------- scalar helpers ----------------
__device__ __forceinline__ u64 fma2(u64 a, u64 b, u64 c) {
    u64 d;
    asm("fma.rn.f32x2 %0, %1, %2, %3;" : "=l"(d) : "l"(a), "l"(b), "l"(c));
    return d;
}
union F2U { float2 f; u64 u; };
__device__ __forceinline__ u64 f2u(float x, float y) { F2U v; v.f = make_float2(x, y); return v.u; }
__device__ __forceinline__ float2 u2f(u64 u) { F2U v; v.u = u; return v.f; }

__device__ __forceinline__ float sigf_(float x) {
    return __fdividef(1.0f, 1.0f + __expf(-x));
}
__device__ __forceinline__ float tanhf_(float x) {
    float e = __expf(2.0f * x);
    return 1.0f - __fdividef(2.0f, e + 1.0f);
}
// pack fp32 -> (bf16 hi | bf16 lo<<16)
__device__ __forceinline__ u32 packsplit(float v) {
    __nv_bfloat16 hi = __float2bfloat16(v);
    __nv_bfloat16 lo = __float2bfloat16(v - __bfloat162float(hi));
    u16 hb = *(u16*)&hi, lb = *(u16*)&lo;
    return (u32)hb | ((u32)lb << 16);
}

__device__ __forceinline__ u32 smem_u32(const void* p) {
    u32 a;
    asm("{ .reg .u64 t; cvta.to.shared.u64 t, %1; cvt.u32.u64 %0, t; }" : "=r"(a) : "l"(p));
    return a;
}

// ---------------- warp-MMA primitives ----------------
#define LDSM4(r0, r1, r2, r3, addr)                                         \
    asm volatile("ldmatrix.sync.aligned.m8n8.x4.shared.b16 {%0,%1,%2,%3}, [%4];" \
        : "=r"(r0), "=r"(r1), "=r"(r2), "=r"(r3) : "r"(addr))

#define MMA16816(d, a, b)                                                   \
    asm volatile("mma.sync.aligned.m16n8k16.row.col.f32.bf16.bf16.f32 "     \
        "{%0,%1,%2,%3}, {%4,%5,%6,%7}, {%8,%9}, {%0,%1,%2,%3};"             \
        : "+f"((d)[0]), "+f"((d)[1]), "+f"((d)[2]), "+f"((d)[3])            \
        : "r"((a)[0]), "r"((a)[1]), "r"((a)[2]), "r"((a)[3]),               \
          "r"((b)[0]), "r"((b)[1]))

// ---------------- fused prep + embed ----------------
#define EMB_BLOCKS 20480

__global__ __launch_bounds__(256) void fused_prep_embed(
    const int* __restrict__ x, const float* __restrict__ emb,
    const float* __restrict__ wih0f, const float* __restrict__ wih0r,
    const float* __restrict__ wih1f,
    const float* __restrict__ bih0f, const float* __restrict__ bhh0f,
    const float* __restrict__ bih0r, const float* __restrict__ bhh0r,
    const float* __restrict__ bih1f, const float* __restrict__ bhh1f)
{
    if (blockIdx.x < EMB_BLOCKS) {
        int id = blockIdx.x * 256 + threadIdx.x;     // 0 .. 65536*80-1
        int bt = id / 80;
        int j = id - bt * 80;
        int ix = x[bt];
        u32 w0 = 0, w1 = 0, w2 = 0, w3 = 0;
        if (j < 75) {
            float4 v = *(const float4*)(emb + (size_t)ix * 300 + j * 4);
            w0 = packsplit(v.x); w1 = packsplit(v.y);
            w2 = packsplit(v.z); w3 = packsplit(v.w);
        }
        *(uint4*)(g_ABw + (size_t)bt * KP1 + j * 4) = make_uint4(w0, w1, w2, w3);
    } else {
        int idx = (blockIdx.x - EMB_BLOCKS) * 256 + threadIdx.x;
        if (idx < 1024 * KP1) {
            int n = idx / KP1, k = idx - n * KP1;
            float v = 0.0f;
            if (k < D_) v = (n < 512) ? wih0f[n * D_ + k] : wih0r[(n - 512) * D_ + k];
            g_B1w[idx] = packsplit(v);
        }
        if (idx < 512 * KP2)
            g_B2w[idx] = packsplit(wih1f[idx]);
        if (idx < 1024)
            g_bias0[idx] = (idx < 512) ? (bih0f[idx] + bhh0f[idx])
                                       : (bih0r[idx - 512] + bhh0r[idx - 512]);
        if (idx < 512)
            g_bias1[idx] = bih1f[idx] + bhh1f[idx];
    }
}

// ---------------- HMMA GEMM, packed-word inputs, 2 CTAs/SM ----------------
// CTA tile M=128 x N=64, 8 warps (4M x 2N), warp tile 32x32, K-chunk 32.
// Double-buffered smem, one __syncthreads per chunk. Same PADK=40 layout
// (proven conflict-free); B tile is a 64-row subset of the audited pattern.
#define PADK 40
#define TILE_A_E (128 * PADK)            // 5120 bf16 elems
#define TILE_B_E (64 * PADK)             // 2560
#define STAGE_E  (2 * TILE_A_E + 2 * TILE_B_E)   // 15360 elems
#define GEMM_SMEM (2 * STAGE_E * 2)      // 61440 bytes

__global__ __launch_bounds__(256, 2) void gemm_mma(
    const u32* __restrict__ A, const u32* __restrict__ B,
    const float* __restrict__ bias, float* __restrict__ C,
    int Kpad, int NC, int N)
{
    extern __shared__ __nv_bfloat16 sg[];

    const int tid = threadIdx.x;
    const int lid = tid & 31, wid = tid >> 5;
    const int wm = wid & 3, wn = wid >> 2;
    const int m0 = blockIdx.y * 128, n0 = blockIdx.x * 64;

    const int gr = tid >> 2, gc = (tid & 3) * 8;     // gc in element-units
    const u32* pA0 = A + (size_t)(m0 + gr) * Kpad + gc;
    const u32* pB0 = B + (size_t)(n0 + gr) * Kpad + gc;   // only gr<64 rows used
    const size_t rstep = (size_t)64 * Kpad;

    const int aRow = wm * 32 + (lid & 7) + ((lid >> 3) & 1) * 8;
    const int aK   = (lid >> 4) * 8;
    const int bRow = wn * 32 + (lid & 7) + ((lid >> 4) & 1) * 8;
    const int bK   = ((lid >> 3) & 1) * 8;
    const u32 sbase = smem_u32(sg);
    const u32 aOff = (u32)(aRow * (PADK * 2) + aK * 2);
    const u32 bOff = (u32)(bRow * (PADK * 2) + bK * 2);

    float acc[2][4][4];
#pragma unroll
    for (int mt = 0; mt < 2; mt++)
#pragma unroll
        for (int nt = 0; nt < 4; nt++)
#pragma unroll
            for (int j = 0; j < 4; j++) acc[mt][nt][j] = 0.0f;

    uint4 wa[2][2], wb[2];
#pragma unroll
    for (int i = 0; i < 2; i++) {
        wa[i][0] = *(const uint4*)(pA0 + i * rstep);
        wa[i][1] = *(const uint4*)(pA0 + i * rstep + 4);
    }
    if (gr < 64) {
        wb[0] = *(const uint4*)(pB0);
        wb[1] = *(const uint4*)(pB0 + 4);
    }

    for (int c = 0; c < NC; c++) {
        __nv_bfloat16* dst = sg + (c & 1) * STAGE_E;
#pragma unroll
        for (int i = 0; i < 2; i++) {
            int so = (gr + i * 64) * PADK + gc;
            uint4 hiA, loA;
            hiA.x = __byte_perm(wa[i][0].x, wa[i][0].y, 0x5410);
            hiA.y = __byte_perm(wa[i][0].z, wa[i][0].w, 0x5410);
            hiA.z = __byte_perm(wa[i][1].x, wa[i][1].y, 0x5410);
            hiA.w = __byte_perm(wa[i][1].z, wa[i][1].w, 0x5410);
            loA.x = __byte_perm(wa[i][0].x, wa[i][0].y, 0x7632);
            loA.y = __byte_perm(wa[i][0].z, wa[i][0].w, 0x7632);
            loA.z = __byte_perm(wa[i][1].x, wa[i][1].y, 0x7632);
            loA.w = __byte_perm(wa[i][1].z, wa[i][1].w, 0x7632);
            *(uint4*)(dst + so)            = *(uint4*)&hiA;
            *(uint4*)(dst + TILE_A_E + so) = *(uint4*)&loA;
        }
        if (gr < 64) {
            int so = gr * PADK + gc;
            uint4 hiB, loB;
            hiB.x = __byte_perm(wb[0].x, wb[0].y, 0x5410);
            hiB.y = __byte_perm(wb[0].z, wb[0].w, 0x5410);
            hiB.z = __byte_perm(wb[1].x, wb[1].y, 0x5410);
            hiB.w = __byte_perm(wb[1].z, wb[1].w, 0x5410);
            loB.x = __byte_perm(wb[0].x, wb[0].y, 0x7632);
            loB.y = __byte_perm(wb[0].z, wb[0].w, 0x7632);
            loB.z = __byte_perm(wb[1].x, wb[1].y, 0x7632);
            loB.w = __byte_perm(wb[1].z, wb[1].w, 0x7632);
            *(uint4*)(dst + 2 * TILE_A_E + so)            = *(uint4*)&hiB;
            *(uint4*)(dst + 2 * TILE_A_E + TILE_B_E + so) = *(uint4*)&loB;
        }
        __syncthreads();
        if (c + 1 < NC) {
            int k0 = (c + 1) * 32;
#pragma unroll
            for (int i = 0; i < 2; i++) {
                wa[i][0] = *(const uint4*)(pA0 + i * rstep + k0);
                wa[i][1] = *(const uint4*)(pA0 + i * rstep + k0 + 4);
            }
            if (gr < 64) {
                wb[0] = *(const uint4*)(pB0 + k0);
                wb[1] = *(const uint4*)(pB0 + k0 + 4);
            }
        }
        const u32 bb = sbase + (c & 1) * (STAGE_E * 2);
#pragma unroll
        for (int ks = 0; ks < 2; ks++) {
            const u32 kso = ks * 32;
            u32 afh[2][4], afl[2][4];
#pragma unroll
            for (int mt = 0; mt < 2; mt++) {
                u32 off = aOff + mt * 16 * (PADK * 2) + kso;
                LDSM4(afh[mt][0], afh[mt][1], afh[mt][2], afh[mt][3], bb + off);
                LDSM4(afl[mt][0], afl[mt][1], afl[mt][2], afl[mt][3], bb + TILE_A_E * 2 + off);
            }
            u32 bfh[2][4], bfl[2][4];
#pragma unroll
            for (int np = 0; np < 2; np++) {
                u32 off = bOff + np * 16 * (PADK * 2) + kso;
                LDSM4(bfh[np][0], bfh[np][1], bfh[np][2], bfh[np][3],
                      bb + 2 * TILE_A_E * 2 + off);
                LDSM4(bfl[np][0], bfl[np][1], bfl[np][2], bfl[np][3],
                      bb + (2 * TILE_A_E + TILE_B_E) * 2 + off);
            }
#pragma unroll
            for (int mt = 0; mt < 2; mt++) {
#pragma unroll
                for (int np = 0; np < 2; np++) {
#pragma unroll
                    for (int hf = 0; hf < 2; hf++) {
                        int nt = np * 2 + hf;
                        u32 bh[2] = { bfh[np][hf * 2], bfh[np][hf * 2 + 1] };
                        u32 bl[2] = { bfl[np][hf * 2], bfl[np][hf * 2 + 1] };
                        MMA16816(acc[mt][nt], afh[mt], bh);
                        MMA16816(acc[mt][nt], afh[mt], bl);
                        MMA16816(acc[mt][nt], afl[mt], bh);
                    }
                }
            }
        }
    }

    const int qr = lid >> 2, qc = (lid & 3) * 2;
#pragma unroll
    for (int mt = 0; mt < 2; mt++) {
#pragma unroll
        for (int nt = 0; nt < 4; nt++) {
            int row = m0 + wm * 32 + mt * 16 + qr;
            int col = n0 + wn * 32 + nt * 8 + qc;
            float b0 = bias[col], b1 = bias[col + 1];
            float2 o0 = make_float2(acc[mt][nt][0] + b0, acc[mt][nt][1] + b1);
            float2 o1 = make_float2(acc[mt][nt][2] + b0, acc[mt][nt][3] + b1);
            *(float2*)(C + (size_t)row * N + col) = o0;
            *(float2*)(C + (size_t)(row + 8) * N + col) = o1;
        }
    }
}

// ---------------- LSTM recurrence (exact R9/R15) ----------------
template<bool STORE_ALL, int NB, int XSTR, int CREGT>
__global__ __launch_bounds__(256, 1) void lstm_rec2(
    const float* __restrict__ xg, int goff,
    const float* __restrict__ whh_f, const float* __restrict__ whh_r,
    const float* __restrict__ wihr, const float* __restrict__ bihr,
    const float* __restrict__ bhhr,
    const float* __restrict__ fcw, const float* __restrict__ fcb,
    float* __restrict__ outp)
{
    const int QRn = CREGT / 4;
    const int QSn = (128 - CREGT) / 4;

    extern __shared__ float sm[];
    float4* wsm  = (float4*)sm;                    // [QSn][2][256]
    float*  h_sm = sm + QSn * 2 * 256 * 4;         // [NB][128]
    float*  gsm  = h_sm + NB * 128;                // [NB][512]

    const int tid = threadIdx.x;
    const int dir = blockIdx.y;
    const int b0 = blockIdx.x * NB;
    const float* whh = dir ? whh_r : whh_f;
    const int go = dir ? goff : 0;

    u64 w0[CREGT / 2], w1[CREGT / 2];
    {
        const float4* wr0 = (const float4*)(whh + (size_t)tid * 128);
        const float4* wr1 = (const float4*)(whh + (size_t)(tid + 256) * 128);
#pragma unroll
        for (int q = 0; q < QRn; q++) {
            float4 v0 = wr0[q], v1 = wr1[q];
            w0[2 * q] = f2u(v0.x, v0.y); w0[2 * q + 1] = f2u(v0.z, v0.w);
            w1[2 * q] = f2u(v1.x, v1.y); w1[2 * q + 1] = f2u(v1.z, v1.w);
        }
#pragma unroll
        for (int q = 0; q < QSn; q++) {
            wsm[(q * 2 + 0) * 256 + tid] = wr0[QRn + q];
            wsm[(q * 2 + 1) * 256 + tid] = wr1[QRn + q];
        }
    }
    if (tid < NB * 128) h_sm[tid] = 0.0f;
    float creg = 0.0f;

    const int t0 = dir ? (T_ - 1) : 0;
    const int tstep = dir ? -1 : 1;
    const float* px[NB];
#pragma unroll
    for (int u = 0; u < NB; u++)
        px[u] = xg + (size_t)(b0 + u) * T_ * XSTR + go + tid;
    long toff = (long)t0 * XSTR;
    const long tdelta = (long)tstep * XSTR;

    float xv[2][NB], xn[2][NB];
#pragma unroll
    for (int u = 0; u < NB; u++) {
        xv[0][u] = px[u][toff];
        xv[1][u] = px[u][toff + 256];
    }
    __syncthreads();

    for (int s = 0; s < T_; s++) {
        const int t = t0 + s * tstep;
        if (s + 1 < T_) {
            long tn = toff + tdelta;
#pragma unroll
            for (int u = 0; u < NB; u++) {
                xn[0][u] = px[u][tn];
                xn[1][u] = px[u][tn + 256];
            }
            toff = tn;
        }

        u64 a0[NB], a1[NB];
#pragma unroll
        for (int u = 0; u < NB; u++) { a0[u] = 0ull; a1[u] = 0ull; }

        // smem-held weight cols first (LDS issued early), then register cols
#pragma unroll
        for (int q = 0; q < QSn; q++) {
            float4 q0 = wsm[(q * 2 + 0) * 256 + tid];
            float4 q1 = wsm[(q * 2 + 1) * 256 + tid];
            u64 w0a = f2u(q0.x, q0.y), w0b = f2u(q0.z, q0.w);
            u64 w1a = f2u(q1.x, q1.y), w1b = f2u(q1.z, q1.w);
#pragma unroll
            for (int u = 0; u < NB; u++) {
                float4 h = *(const float4*)(h_sm + u * 128 + (QRn + q) * 4);
                u64 ha = f2u(h.x, h.y), hb = f2u(h.z, h.w);
                a0[u] = fma2(w0a, ha, a0[u]); a0[u] = fma2(w0b, hb, a0[u]);
                a1[u] = fma2(w1a, ha, a1[u]); a1[u] = fma2(w1b, hb, a1[u]);
            }
        }
#pragma unroll
        for (int q = 0; q < QRn; q++) {
#pragma unroll
            for (int u = 0; u < NB; u++) {
                float4 h = *(const float4*)(h_sm + u * 128 + q * 4);
                u64 ha = f2u(h.x, h.y), hb = f2u(h.z, h.w);
                a0[u] = fma2(w0[2 * q], ha, a0[u]); a0[u] = fma2(w0[2 * q + 1], hb, a0[u]);
                a1[u] = fma2(w1[2 * q], ha, a1[u]); a1[u] = fma2(w1[2 * q + 1], hb, a1[u]);
            }
        }
#pragma unroll
        for (int u = 0; u < NB; u++) {
            float2 r0 = u2f(a0[u]), r1 = u2f(a1[u]);
            gsm[u * 512 + tid]       = r0.x + r0.y + xv[0][u];
            gsm[u * 512 + tid + 256] = r1.x + r1.y + xv[1][u];
        }
        __syncthreads();

        if (NB == 2 || tid < 128) {
            const int bb = (NB == 2) ? (tid >> 7) : 0;
            const int n = tid & 127;
            const float* gs = gsm + bb * 512;
            float iv = sigf_(gs[n]);
            float fv = sigf_(gs[n + 128]);
            float gv = tanhf_(gs[n + 256]);
            float ov = sigf_(gs[n + 384]);
            creg = fv * creg + iv * gv;
            float hv = ov * tanhf_(creg);
            h_sm[bb * 128 + n] = hv;
            if (STORE_ALL) {
                size_t o = ((size_t)(b0 + bb) * T_ + t) * 256 + dir * 128 + n;
                g_h0w[o] = packsplit(hv);
                if (t == T_ - 1) g_h0[o] = hv;
            }
        }
        __syncthreads();
#pragma unroll
        for (int u = 0; u < NB; u++) { xv[0][u] = xn[0][u]; xv[1][u] = xn[1][u]; }
    }

    // ---- fused tail (NB==1): layer1 reverse first step + FC head ----
    if (!STORE_ALL) {
        float* h0c = gsm + 512;                     // [256] scratch
        const int b = b0;
        h0c[tid] = g_h0[((size_t)b * T_ + (T_ - 1)) * 256 + tid];
        __syncthreads();

        u64 ac0 = 0ull, ac1 = 0ull;
        const float4* wr0 = (const float4*)(wihr + (size_t)tid * 256);
        const float4* wr1 = (const float4*)(wihr + (size_t)(tid + 256) * 256);
        const float4* hp = (const float4*)h0c;
#pragma unroll 8
        for (int q = 0; q < 64; q++) {
            float4 h = hp[q];
            u64 ha = f2u(h.x, h.y), hb = f2u(h.z, h.w);
            float4 v0 = wr0[q];
            ac0 = fma2(f2u(v0.x, v0.y), ha, ac0);
            ac0 = fma2(f2u(v0.z, v0.w), hb, ac0);
            float4 v1 = wr1[q];
            ac1 = fma2(f2u(v1.x, v1.y), ha, ac1);
            ac1 = fma2(f2u(v1.z, v1.w), hb, ac1);
        }
        {
            float2 r0 = u2f(ac0), r1 = u2f(ac1);
            gsm[tid]       = r0.x + r0.y + bihr[tid] + bhhr[tid];
            gsm[tid + 256] = r1.x + r1.y + bihr[tid + 256] + bhhr[tid + 256];
        }
        __syncthreads();
        if (tid < 128) {
            float iv = sigf_(gsm[tid]);
            float gv = tanhf_(gsm[tid + 256]);
            float ov = sigf_(gsm[tid + 384]);
            float cc = iv * gv;                     // f*c0 = 0 on first reverse step
            float hrev = ov * tanhf_(cc);
            float h1fv = h_sm[tid];
            h0c[tid] = h1fv;
            h0c[128 + tid] = hrev;
        }
        __syncthreads();
        if (tid < 10) {
            float a = fcb[tid];
            const float* w = fcw + tid * 256;
#pragma unroll 8
            for (int j = 0; j < 256; j++) a += w[j] * h0c[j];
            outp[b * 10 + tid] = a;
        }
    }
}

// ---------------- launch ----------------
extern "C" void kernel_launch(void* const* d_in, const int* in_sizes, int n_in,
                              void* d_out, int out_size)
{
    const int*   x     = (const int*)d_in[0];
    const float* emb   = (const float*)d_in[1];
    const float* wih0f = (const float*)d_in[2];
    const float* whh0f = (const float*)d_in[3];
    const float* bih0f = (const float*)d_in[4];
    const float* bhh0f = (const float*)d_in[5];
    const float* wih0r = (const float*)d_in[6];
    const float* whh0r = (const float*)d_in[7];
    const float* bih0r = (const float*)d_in[8];
    const float* bhh0r = (const float*)d_in[9];
    const float* wih1f = (const float*)d_in[10];
    const float* whh1f = (const float*)d_in[11];
    const float* bih1f = (const float*)d_in[12];
    const float* bhh1f = (const float*)d_in[13];
    const float* wih1r = (const float*)d_in[14];
    const float* bih1r = (const float*)d_in[16];
    const float* bhh1r = (const float*)d_in[17];
    const float* fc_w  = (const float*)d_in[18];
    const float* fc_b  = (const float*)d_in[19];
    float* out = (float*)d_out;

    void *ABw_p, *xg0_p, *h0_p, *h0w_p, *xg1_p, *B1w_p, *B2w_p, *bias0_p, *bias1_p;
    cudaGetSymbolAddress(&ABw_p,  g_ABw);
    cudaGetSymbolAddress(&xg0_p,  g_xg0);
    cudaGetSymbolAddress(&h0_p,   g_h0);
    cudaGetSymbolAddress(&h0w_p,  g_h0w);
    cudaGetSymbolAddress(&xg1_p,  g_xg1);
    cudaGetSymbolAddress(&B1w_p,  g_B1w);
    cudaGetSymbolAddress(&B2w_p,  g_B2w);
    cudaGetSymbolAddress(&bias0_p, g_bias0);
    cudaGetSymbolAddress(&bias1_p, g_bias1);

    // NB=2, CREG=96: wsm 8 q -> 65536B; h 1024; gates 4096
    const int rec_smem2 = 8 * 2 * 256 * 16 + 2 * 128 * 4 + 2 * 512 * 4;
    // NB=1, CREG=100: wsm 7 q -> 57344B; h 512; gates 2048; h0c 1024
    const int rec_smem1 = 7 * 2 * 256 * 16 + 1 * 128 * 4 + 1 * 512 * 4 + 256 * 4;
    cudaFuncSetAttribute(lstm_rec2<true, 2, 1024, 96>,
                         cudaFuncAttributeMaxDynamicSharedMemorySize, rec_smem2);
    cudaFuncSetAttribute(lstm_rec2<false, 1, 512, 100>,
                         cudaFuncAttributeMaxDynamicSharedMemorySize, rec_smem1);
    cudaFuncSetAttribute(gemm_mma, cudaFuncAttributeMaxDynamicSharedMemorySize, GEMM_SMEM);

    // 1. fused weight prep + embedding gather (packed bf16 hi|lo words)
    fused_prep_embed<<<EMB_BLOCKS + 1280, 256>>>(
        x, emb, wih0f, wih0r, wih1f,
        bih0f, bhh0f, bih0r, bhh0r, bih1f, bhh1f);
    // 2. layer0 input GEMM (HMMA, 2 CTA/SM): [65536,320] x [320,1024]
    gemm_mma<<<dim3(16, 512), 256, GEMM_SMEM>>>(
        (const u32*)ABw_p, (const u32*)B1w_p,
        (const float*)bias0_p, (float*)xg0_p, KP1, 10, 1024);
    // 3. layer0 recurrence (NB=2, both dirs -> 128 CTAs of 256 threads)
    lstm_rec2<true, 2, 1024, 96><<<dim3(64, 2), 256, rec_smem2>>>(
        (const float*)xg0_p, 512, whh0f, whh0r,
        nullptr, nullptr, nullptr, nullptr, nullptr, nullptr);
    // 4. layer1-fwd input GEMM (HMMA, 2 CTA/SM): [65536,256] x [256,512]
    gemm_mma<<<dim3(8, 512), 256, GEMM_SMEM>>>(
        (const u32*)h0w_p, (const u32*)B2w_p,
        (const float*)bias1_p, (float*)xg1_p, KP2, 8, 512);
    // 5. layer1-fwd recurrence + fused tail (reverse first step + FC head)
    lstm_rec2<false, 1, 512, 100><<<dim3(128, 1), 256, rec_smem1>>>(
        (const float*)xg1_p, 0, whh1f, whh1f,
        wih1r, bih1r, bhh1r, fc_w, fc_b, out);
}

// round 17
// speedup vs baseline: 1.0127x; 1.0127x over previous
#include <cuda_runtime.h>
#include <cuda_bf16.h>

typedef unsigned long long u64;
typedef unsigned int u32;
typedef unsigned short u16;

#define B_  128
#define T_  512
#define D_  300
#define H_  128
#define KP1 320   // layer0 K padded (300 -> 320, 10 chunks of 32)
#define KP2 256   // layer1 K (8 chunks of 32)

// ---------------- static device scratch ----------------
// bf16 hi/lo interleaved as one u32 word per element: word = hi_bits | (lo_bits << 16)
__device__ u32   g_ABw [(size_t)B_ * T_ * KP1];    // embeddings packed
__device__ float g_xg0 [(size_t)B_ * T_ * 1024];   // layer0 preacts (fwd 0:512, rev 512:1024)
__device__ float g_h0  [(size_t)B_ * T_ * 256];    // layer0 output fp32 (only t=T-1 written)
__device__ u32   g_h0w [(size_t)B_ * T_ * 256];    // layer0 output packed
__device__ float g_xg1 [(size_t)B_ * T_ * 512];    // layer1-fwd preacts
__device__ u32   g_B1w [1024 * KP1];               // W_ih layer0 (f||r), [n][k] packed
__device__ u32   g_B2w [512 * KP2];                // W_ih layer1-fwd, [n][k] packed
__device__ float g_bias0[1024];
__device__ float g_bias1[512];

// ---------------- scalar helpers ----------------
__device__ __forceinline__ u64 fma2(u64 a, u64 b, u64 c) {
    u64 d;
    asm("fma.rn.f32x2 %0, %1, %2, %3;" : "=l"(d) : "l"(a), "l"(b), "l"(c));
    return d;
}
union F2U { float2 f; u64 u; };
__device__ __forceinline__ u64 f2u(float x, float y) { F2U v; v.f = make_float2(x, y); return v.u; }
__device__ __forceinline__ float2 u2f(u64 u) { F2U v; v.u = u; return v.f; }

__device__ __forceinline__ float sigf_(float x) {
    return __fdividef(1.0f, 1.0f + __expf(-x));
}
__device__ __forceinline__ float tanhf_(float x) {
    float e = __expf(2.0f * x);
    return 1.0f - __fdividef(2.0f, e + 1.0f);
}
// pack fp32 -> (bf16 hi | bf16 lo<<16)
__device__ __forceinline__ u32 packsplit(float v) {
    __nv_bfloat16 hi = __float2bfloat16(v);
    __nv_bfloat16 lo = __float2bfloat16(v - __bfloat162float(hi));
    u16 hb = *(u16*)&hi, lb = *(u16*)&lo;
    return (u32)hb | ((u32)lb << 16);
}

__device__ __forceinline__ u32 smem_u32(const void* p) {
    u32 a;
    asm("{ .reg .u64 t; cvta.to.shared.u64 t, %1; cvt.u32.u64 %0, t; }" : "=r"(a) : "l"(p));
    return a;
}

// ---------------- warp-MMA primitives ----------------
#define LDSM4(r0, r1, r2, r3, addr)                                         \
    asm volatile("ldmatrix.sync.aligned.m8n8.x4.shared.b16 {%0,%1,%2,%3}, [%4];" \
        : "=r"(r0), "=r"(r1), "=r"(r2), "=r"(r3) : "r"(addr))

#define MMA16816(d, a, b)                                                   \
    asm volatile("mma.sync.aligned.m16n8k16.row.col.f32.bf16.bf16.f32 "     \
        "{%0,%1,%2,%3}, {%4,%5,%6,%7}, {%8,%9}, {%0,%1,%2,%3};"             \
        : "+f"((d)[0]), "+f"((d)[1]), "+f"((d)[2]), "+f"((d)[3])            \
        : "r"((a)[0]), "r"((a)[1]), "r"((a)[2]), "r"((a)[3]),               \
          "r"((b)[0]), "r"((b)[1]))

// ---------------- fused prep + embed ----------------
#define EMB_BLOCKS 20480

__global__ __launch_bounds__(256) void fused_prep_embed(
    const int* __restrict__ x, const float* __restrict__ emb,
    const float* __restrict__ wih0f, const float* __restrict__ wih0r,
    const float* __restrict__ wih1f,
    const float* __restrict__ bih0f, const float* __restrict__ bhh0f,
    const float* __restrict__ bih0r, const float* __restrict__ bhh0r,
    const float* __restrict__ bih1f, const float* __restrict__ bhh1f)
{
    if (blockIdx.x < EMB_BLOCKS) {
        int id = blockIdx.x * 256 + threadIdx.x;     // 0 .. 65536*80-1
        int bt = id / 80;
        int j = id - bt * 80;
        int ix = x[bt];
        u32 w0 = 0, w1 = 0, w2 = 0, w3 = 0;
        if (j < 75) {
            float4 v = *(const float4*)(emb + (size_t)ix * 300 + j * 4);
            w0 = packsplit(v.x); w1 = packsplit(v.y);
            w2 = packsplit(v.z); w3 = packsplit(v.w);
        }
        *(uint4*)(g_ABw + (size_t)bt * KP1 + j * 4) = make_uint4(w0, w1, w2, w3);
    } else {
        int idx = (blockIdx.x - EMB_BLOCKS) * 256 + threadIdx.x;
        if (idx < 1024 * KP1) {
            int n = idx / KP1, k = idx - n * KP1;
            float v = 0.0f;
            if (k < D_) v = (n < 512) ? wih0f[n * D_ + k] : wih0r[(n - 512) * D_ + k];
            g_B1w[idx] = packsplit(v);
        }
        if (idx < 512 * KP2)
            g_B2w[idx] = packsplit(wih1f[idx]);
        if (idx < 1024)
            g_bias0[idx] = (idx < 512) ? (bih0f[idx] + bhh0f[idx])
                                       : (bih0r[idx - 512] + bhh0r[idx - 512]);
        if (idx < 512)
            g_bias1[idx] = bih1f[idx] + bhh1f[idx];
    }
}

// ---------------- HMMA GEMM, packed-word inputs ----------------
// CTA 128x128, 8 warps (4M x 2N), warp tile 32x64, K-chunk 32.
// Double-buffered smem, one __syncthreads per chunk. PRMT unpack on store.
#define PADK 40
#define TILE_ELEMS (128 * PADK)
#define BUF_ELEMS  (4 * TILE_ELEMS)
#define GEMM_SMEM  (2 * BUF_ELEMS * 2)

__global__ __launch_bounds__(256) void gemm_mma(
    const u32* __restrict__ A, const u32* __restrict__ B,
    const float* __restrict__ bias, float* __restrict__ C,
    int Kpad, int NC, int N)
{
    extern __shared__ __nv_bfloat16 sg[];

    const int tid = threadIdx.x;
    const int lid = tid & 31, wid = tid >> 5;
    const int wm = wid & 3, wn = wid >> 2;
    const int m0 = blockIdx.y * 128, n0 = blockIdx.x * 128;

    const int gr = tid >> 2, gc = (tid & 3) * 8;     // gc in element-units
    const u32* pA0 = A + (size_t)(m0 + gr) * Kpad + gc;
    const u32* pB0 = B + (size_t)(n0 + gr) * Kpad + gc;
    const size_t rstep = (size_t)64 * Kpad;

    const int aRow = wm * 32 + (lid & 7) + ((lid >> 3) & 1) * 8;
    const int aK   = (lid >> 4) * 8;
    const int bRow = wn * 64 + (lid & 7) + ((lid >> 4) & 1) * 8;
    const int bK   = ((lid >> 3) & 1) * 8;
    const u32 sbase = smem_u32(sg);
    const u32 aOff = (u32)(aRow * (PADK * 2) + aK * 2);
    const u32 bOff = (u32)(bRow * (PADK * 2) + bK * 2);

    float acc[2][8][4];
#pragma unroll
    for (int mt = 0; mt < 2; mt++)
#pragma unroll
        for (int nt = 0; nt < 8; nt++)
#pragma unroll
            for (int j = 0; j < 4; j++) acc[mt][nt][j] = 0.0f;

    uint4 wa[2][2], wb[2][2];      // [row-group][half of 8 words]
#pragma unroll
    for (int i = 0; i < 2; i++) {
        wa[i][0] = *(const uint4*)(pA0 + i * rstep);
        wa[i][1] = *(const uint4*)(pA0 + i * rstep + 4);
        wb[i][0] = *(const uint4*)(pB0 + i * rstep);
        wb[i][1] = *(const uint4*)(pB0 + i * rstep + 4);
    }

    for (int c = 0; c < NC; c++) {
        __nv_bfloat16* dst = sg + (c & 1) * BUF_ELEMS;
#pragma unroll
        for (int i = 0; i < 2; i++) {
            int so = (gr + i * 64) * PADK + gc;
            uint4 hiA, loA, hiB, loB;
            hiA.x = __byte_perm(wa[i][0].x, wa[i][0].y, 0x5410);
            hiA.y = __byte_perm(wa[i][0].z, wa[i][0].w, 0x5410);
            hiA.z = __byte_perm(wa[i][1].x, wa[i][1].y, 0x5410);
            hiA.w = __byte_perm(wa[i][1].z, wa[i][1].w, 0x5410);
            loA.x = __byte_perm(wa[i][0].x, wa[i][0].y, 0x7632);
            loA.y = __byte_perm(wa[i][0].z, wa[i][0].w, 0x7632);
            loA.z = __byte_perm(wa[i][1].x, wa[i][1].y, 0x7632);
            loA.w = __byte_perm(wa[i][1].z, wa[i][1].w, 0x7632);
            hiB.x = __byte_perm(wb[i][0].x, wb[i][0].y, 0x5410);
            hiB.y = __byte_perm(wb[i][0].z, wb[i][0].w, 0x5410);
            hiB.z = __byte_perm(wb[i][1].x, wb[i][1].y, 0x5410);
            hiB.w = __byte_perm(wb[i][1].z, wb[i][1].w, 0x5410);
            loB.x = __byte_perm(wb[i][0].x, wb[i][0].y, 0x7632);
            loB.y = __byte_perm(wb[i][0].z, wb[i][0].w, 0x7632);
            loB.z = __byte_perm(wb[i][1].x, wb[i][1].y, 0x7632);
            loB.w = __byte_perm(wb[i][1].z, wb[i][1].w, 0x7632);
            *(uint4*)(dst + so)                  = *(uint4*)&hiA;
            *(uint4*)(dst + TILE_ELEMS + so)     = *(uint4*)&loA;
            *(uint4*)(dst + 2 * TILE_ELEMS + so) = *(uint4*)&hiB;
            *(uint4*)(dst + 3 * TILE_ELEMS + so) = *(uint4*)&loB;
        }
        __syncthreads();
        if (c + 1 < NC) {
            int k0 = (c + 1) * 32;
#pragma unroll
            for (int i = 0; i < 2; i++) {
                wa[i][0] = *(const uint4*)(pA0 + i * rstep + k0);
                wa[i][1] = *(const uint4*)(pA0 + i * rstep + k0 + 4);
                wb[i][0] = *(const uint4*)(pB0 + i * rstep + k0);
                wb[i][1] = *(const uint4*)(pB0 + i * rstep + k0 + 4);
            }
        }
        const u32 bb = sbase + (c & 1) * (BUF_ELEMS * 2);
#pragma unroll
        for (int ks = 0; ks < 2; ks++) {
            const u32 kso = ks * 32;
            u32 afh[2][4], afl[2][4];
#pragma unroll
            for (int mt = 0; mt < 2; mt++) {
                u32 off = aOff + mt * 16 * (PADK * 2) + kso;
                LDSM4(afh[mt][0], afh[mt][1], afh[mt][2], afh[mt][3], bb + off);
                LDSM4(afl[mt][0], afl[mt][1], afl[mt][2], afl[mt][3], bb + TILE_ELEMS * 2 + off);
            }
            u32 bfh[4][4], bfl[4][4];
#pragma unroll
            for (int np = 0; np < 4; np++) {
                u32 off = bOff + np * 16 * (PADK * 2) + kso;
                LDSM4(bfh[np][0], bfh[np][1], bfh[np][2], bfh[np][3], bb + 2 * TILE_ELEMS * 2 + off);
                LDSM4(bfl[np][0], bfl[np][1], bfl[np][2], bfl[np][3], bb + 3 * TILE_ELEMS * 2 + off);
            }
#pragma unroll
            for (int mt = 0; mt < 2; mt++) {
#pragma unroll
                for (int np = 0; np < 4; np++) {
#pragma unroll
                    for (int hf = 0; hf < 2; hf++) {
                        int nt = np * 2 + hf;
                        u32 bh[2] = { bfh[np][hf * 2], bfh[np][hf * 2 + 1] };
                        u32 bl[2] = { bfl[np][hf * 2], bfl[np][hf * 2 + 1] };
                        MMA16816(acc[mt][nt], afh[mt], bh);
                        MMA16816(acc[mt][nt], afh[mt], bl);
                        MMA16816(acc[mt][nt], afl[mt], bh);
                    }
                }
            }
        }
    }

    const int qr = lid >> 2, qc = (lid & 3) * 2;
#pragma unroll
    for (int mt = 0; mt < 2; mt++) {
#pragma unroll
        for (int nt = 0; nt < 8; nt++) {
            int row = m0 + wm * 32 + mt * 16 + qr;
            int col = n0 + wn * 64 + nt * 8 + qc;
            float b0 = bias[col], b1 = bias[col + 1];
            float2 o0 = make_float2(acc[mt][nt][0] + b0, acc[mt][nt][1] + b1);
            float2 o1 = make_float2(acc[mt][nt][2] + b0, acc[mt][nt][3] + b1);
            *(float2*)(C + (size_t)row * N + col) = o0;
            *(float2*)(C + (size_t)(row + 8) * N + col) = o1;
        }
    }
}

// ---------------- LSTM recurrence (R6 structure, CREG templated) ----------------
// 256 threads, thread owns rows (tid, tid+256). CREGT cols/row in regs, rest in smem.
// NB=1 instantiation fuses the layer1-reverse-first-step + FC tail at the end.
template<bool STORE_ALL, int NB, int XSTR, int CREGT>
__global__ __launch_bounds__(256, 1) void lstm_rec2(
    const float* __restrict__ xg, int goff,
    const float* __restrict__ whh_f, const float* __restrict__ whh_r,
    const float* __restrict__ wihr, const float* __restrict__ bihr,
    const float* __restrict__ bhhr,
    const float* __restrict__ fcw, const float* __restrict__ fcb,
    float* __restrict__ outp)
{
    const int QRn = CREGT / 4;
    const int QSn = (128 - CREGT) / 4;

    extern __shared__ float sm[];
    float4* wsm  = (float4*)sm;                    // [QSn][2][256]
    float*  h_sm = sm + QSn * 2 * 256 * 4;         // [NB][128]
    float*  gsm  = h_sm + NB * 128;                // [NB][512]

    const int tid = threadIdx.x;
    const int dir = blockIdx.y;
    const int b0 = blockIdx.x * NB;
    const float* whh = dir ? whh_r : whh_f;
    const int go = dir ? goff : 0;

    u64 w0[CREGT / 2], w1[CREGT / 2];
    {
        const float4* wr0 = (const float4*)(whh + (size_t)tid * 128);
        const float4* wr1 = (const float4*)(whh + (size_t)(tid + 256) * 128);
#pragma unroll
        for (int q = 0; q < QRn; q++) {
            float4 v0 = wr0[q], v1 = wr1[q];
            w0[2 * q] = f2u(v0.x, v0.y); w0[2 * q + 1] = f2u(v0.z, v0.w);
            w1[2 * q] = f2u(v1.x, v1.y); w1[2 * q + 1] = f2u(v1.z, v1.w);
        }
#pragma unroll
        for (int q = 0; q < QSn; q++) {
            wsm[(q * 2 + 0) * 256 + tid] = wr0[QRn + q];
            wsm[(q * 2 + 1) * 256 + tid] = wr1[QRn + q];
        }
    }
    if (tid < NB * 128) h_sm[tid] = 0.0f;
    float creg = 0.0f;

    const int t0 = dir ? (T_ - 1) : 0;
    const int tstep = dir ? -1 : 1;
    const float* px[NB];
#pragma unroll
    for (int u = 0; u < NB; u++)
        px[u] = xg + (size_t)(b0 + u) * T_ * XSTR + go + tid;
    long toff = (long)t0 * XSTR;
    const long tdelta = (long)tstep * XSTR;

    float xv[2][NB], xn[2][NB];
#pragma unroll
    for (int u = 0; u < NB; u++) {
        xv[0][u] = px[u][toff];
        xv[1][u] = px[u][toff + 256];
    }
    __syncthreads();

    for (int s = 0; s < T_; s++) {
        const int t = t0 + s * tstep;
        if (s + 1 < T_) {
            long tn = toff + tdelta;
#pragma unroll
            for (int u = 0; u < NB; u++) {
                xn[0][u] = px[u][tn];
                xn[1][u] = px[u][tn + 256];
            }
            toff = tn;
        }

        u64 a0[NB], a1[NB];
#pragma unroll
        for (int u = 0; u < NB; u++) { a0[u] = 0ull; a1[u] = 0ull; }

        // smem-held weight cols first (LDS issued early), then register cols
#pragma unroll
        for (int q = 0; q < QSn; q++) {
            float4 q0 = wsm[(q * 2 + 0) * 256 + tid];
            float4 q1 = wsm[(q * 2 + 1) * 256 + tid];
            u64 w0a = f2u(q0.x, q0.y), w0b = f2u(q0.z, q0.w);
            u64 w1a = f2u(q1.x, q1.y), w1b = f2u(q1.z, q1.w);
#pragma unroll
            for (int u = 0; u < NB; u++) {
                float4 h = *(const float4*)(h_sm + u * 128 + (QRn + q) * 4);
                u64 ha = f2u(h.x, h.y), hb = f2u(h.z, h.w);
                a0[u] = fma2(w0a, ha, a0[u]); a0[u] = fma2(w0b, hb, a0[u]);
                a1[u] = fma2(w1a, ha, a1[u]); a1[u] = fma2(w1b, hb, a1[u]);
            }
        }
#pragma unroll
        for (int q = 0; q < QRn; q++) {
#pragma unroll
            for (int u = 0; u < NB; u++) {
                float4 h = *(const float4*)(h_sm + u * 128 + q * 4);
                u64 ha = f2u(h.x, h.y), hb = f2u(h.z, h.w);
                a0[u] = fma2(w0[2 * q], ha, a0[u]); a0[u] = fma2(w0[2 * q + 1], hb, a0[u]);
                a1[u] = fma2(w1[2 * q], ha, a1[u]); a1[u] = fma2(w1[2 * q + 1], hb, a1[u]);
            }
        }
#pragma unroll
        for (int u = 0; u < NB; u++) {
            float2 r0 = u2f(a0[u]), r1 = u2f(a1[u]);
            gsm[u * 512 + tid]       = r0.x + r0.y + xv[0][u];
            gsm[u * 512 + tid + 256] = r1.x + r1.y + xv[1][u];
        }
        __syncthreads();

        if (NB == 2 || tid < 128) {
            const int bb = (NB == 2) ? (tid >> 7) : 0;
            const int n = tid & 127;
            const float* gs = gsm + bb * 512;
            float iv = sigf_(gs[n]);
            float fv = sigf_(gs[n + 128]);
            float gv = tanhf_(gs[n + 256]);
            float ov = sigf_(gs[n + 384]);
            creg = fv * creg + iv * gv;
            float hv = ov * tanhf_(creg);
            h_sm[bb * 128 + n] = hv;
            if (STORE_ALL) {
                size_t o = ((size_t)(b0 + bb) * T_ + t) * 256 + dir * 128 + n;
                g_h0w[o] = packsplit(hv);
                if (t == T_ - 1) g_h0[o] = hv;
            }
        }
        __syncthreads();
#pragma unroll
        for (int u = 0; u < NB; u++) { xv[0][u] = xn[0][u]; xv[1][u] = xn[1][u]; }
    }

    // ---- fused tail (NB==1): layer1 reverse first step + FC head ----
    if (!STORE_ALL) {
        float* h0c = gsm + 512;                     // [256] scratch
        const int b = b0;
        h0c[tid] = g_h0[((size_t)b * T_ + (T_ - 1)) * 256 + tid];
        __syncthreads();

        u64 ac0 = 0ull, ac1 = 0ull;
        const float4* wr0 = (const float4*)(wihr + (size_t)tid * 256);
        const float4* wr1 = (const float4*)(wihr + (size_t)(tid + 256) * 256);
        const float4* hp = (const float4*)h0c;
#pragma unroll 8
        for (int q = 0; q < 64; q++) {
            float4 h = hp[q];
            u64 ha = f2u(h.x, h.y), hb = f2u(h.z, h.w);
            float4 v0 = wr0[q];
            ac0 = fma2(f2u(v0.x, v0.y), ha, ac0);
            ac0 = fma2(f2u(v0.z, v0.w), hb, ac0);
            float4 v1 = wr1[q];
            ac1 = fma2(f2u(v1.x, v1.y), ha, ac1);
            ac1 = fma2(f2u(v1.z, v1.w), hb, ac1);
        }
        {
            float2 r0 = u2f(ac0), r1 = u2f(ac1);
            gsm[tid]       = r0.x + r0.y + bihr[tid] + bhhr[tid];
            gsm[tid + 256] = r1.x + r1.y + bihr[tid + 256] + bhhr[tid + 256];
        }
        __syncthreads();
        if (tid < 128) {
            float iv = sigf_(gsm[tid]);
            float gv = tanhf_(gsm[tid + 256]);
            float ov = sigf_(gsm[tid + 384]);
            float cc = iv * gv;                     // f*c0 = 0 on first reverse step
            float hrev = ov * tanhf_(cc);
            float h1fv = h_sm[tid];
            h0c[tid] = h1fv;
            h0c[128 + tid] = hrev;
        }
        __syncthreads();
        if (tid < 10) {
            float a = fcb[tid];
            const float* w = fcw + tid * 256;
#pragma unroll 8
            for (int j = 0; j < 256; j++) a += w[j] * h0c[j];
            outp[b * 10 + tid] = a;
        }
    }
}

// ---------------- launch ----------------
extern "C" void kernel_launch(void* const* d_in, const int* in_sizes, int n_in,
                              void* d_out, int out_size)
{
    const int*   x     = (const int*)d_in[0];
    const float* emb   = (const float*)d_in[1];
    const float* wih0f = (const float*)d_in[2];
    const float* whh0f = (const float*)d_in[3];
    const float* bih0f = (const float*)d_in[4];
    const float* bhh0f = (const float*)d_in[5];
    const float* wih0r = (const float*)d_in[6];
    const float* whh0r = (const float*)d_in[7];
    const float* bih0r = (const float*)d_in[8];
    const float* bhh0r = (const float*)d_in[9];
    const float* wih1f = (const float*)d_in[10];
    const float* whh1f = (const float*)d_in[11];
    const float* bih1f = (const float*)d_in[12];
    const float* bhh1f = (const float*)d_in[13];
    const float* wih1r = (const float*)d_in[14];
    const float* bih1r = (const float*)d_in[16];
    const float* bhh1r = (const float*)d_in[17];
    const float* fc_w  = (const float*)d_in[18];
    const float* fc_b  = (const float*)d_in[19];
    float* out = (float*)d_out;

    void *ABw_p, *xg0_p, *h0_p, *h0w_p, *xg1_p, *B1w_p, *B2w_p, *bias0_p, *bias1_p;
    cudaGetSymbolAddress(&ABw_p,  g_ABw);
    cudaGetSymbolAddress(&xg0_p,  g_xg0);
    cudaGetSymbolAddress(&h0_p,   g_h0);
    cudaGetSymbolAddress(&h0w_p,  g_h0w);
    cudaGetSymbolAddress(&xg1_p,  g_xg1);
    cudaGetSymbolAddress(&B1w_p,  g_B1w);
    cudaGetSymbolAddress(&B2w_p,  g_B2w);
    cudaGetSymbolAddress(&bias0_p, g_bias0);
    cudaGetSymbolAddress(&bias1_p, g_bias1);

    // NB=2, CREG=96: wsm 8 q -> 65536B; h 1024; gates 4096
    const int rec_smem2 = 8 * 2 * 256 * 16 + 2 * 128 * 4 + 2 * 512 * 4;
    // NB=1, CREG=100: wsm 7 q -> 57344B; h 512; gates 2048; h0c 1024
    const int rec_smem1 = 7 * 2 * 256 * 16 + 1 * 128 * 4 + 1 * 512 * 4 + 256 * 4;
    cudaFuncSetAttribute(lstm_rec2<true, 2, 1024, 96>,
                         cudaFuncAttributeMaxDynamicSharedMemorySize, rec_smem2);
    cudaFuncSetAttribute(lstm_rec2<false, 1, 512, 100>,
                         cudaFuncAttributeMaxDynamicSharedMemorySize, rec_smem1);
    cudaFuncSetAttribute(gemm_mma, cudaFuncAttributeMaxDynamicSharedMemorySize, GEMM_SMEM);

    // 1. fused weight prep + embedding gather (packed bf16 hi|lo words)
    fused_prep_embed<<<EMB_BLOCKS + 1280, 256>>>(
        x, emb, wih0f, wih0r, wih1f,
        bih0f, bhh0f, bih0r, bhh0r, bih1f, bhh1f);
    // 2. layer0 input GEMM (HMMA): [65536,320] x [320,1024]
    gemm_mma<<<dim3(8, 512), 256, GEMM_SMEM>>>(
        (const u32*)ABw_p, (const u32*)B1w_p,
        (const float*)bias0_p, (float*)xg0_p, KP1, 10, 1024);
    // 3. layer0 recurrence (NB=2, both dirs -> 128 CTAs of 256 threads)
    lstm_rec2<true, 2, 1024, 96><<<dim3(64, 2), 256, rec_smem2>>>(
        (const float*)xg0_p, 512, whh0f, whh0r,
        nullptr, nullptr, nullptr, nullptr, nullptr, nullptr);
    // 4. layer1-fwd input GEMM (HMMA): [65536,256] x [256,512]
    gemm_mma<<<dim3(4, 512), 256, GEMM_SMEM>>>(
        (const u32*)h0w_p, (const u32*)B2w_p,
        (const float*)bias1_p, (float*)xg1_p, KP2, 8, 512);
    // 5. layer1-fwd recurrence + fused tail (reverse first step + FC head)
    lstm_rec2<false, 1, 512, 100><<<dim3(128, 1), 256, rec_smem1>>>(
        (const float*)xg1_p, 0, whh1f, whh1f,
        wih1r, bih1r, bhh1r, fc_w, fc_b, out);
}